// round 8
// baseline (speedup 1.0000x reference)
#include <cuda_runtime.h>
#include <cuda_bf16.h>
#include <cstdint>
#include <cstddef>

// Problem constants
#define B_    4
#define N_    4096
#define M_    1024
#define QD_   1024
#define CD_   768
#define H_    16
#define D_    64
#define INNER 1024
#define BNQ   (B_ * N_)   // 16384 query rows
#define BMC   (B_ * M_)   // 4096 context rows

// ---------------------------------------------------------------------------
// Static device scratch
// ---------------------------------------------------------------------------
__device__ __nv_bfloat16 g_Qhi[BNQ * INNER], g_Qlo[BNQ * INNER];
__device__ __nv_bfloat16 g_Khi[BMC * INNER], g_Klo[BMC * INNER];
__device__ __nv_bfloat16 g_Vhi[BMC * INNER], g_Vlo[BMC * INNER];

__device__ __nv_bfloat16 g_xhi[BNQ * QD_],  g_xlo[BNQ * QD_];
__device__ __nv_bfloat16 g_chi[BMC * CD_],  g_clo[BMC * CD_];
__device__ __nv_bfloat16 g_WqThi[INNER * QD_], g_WqTlo[INNER * QD_];
__device__ __nv_bfloat16 g_WkThi[INNER * CD_], g_WkTlo[INNER * CD_];
__device__ __nv_bfloat16 g_WvThi[INNER * CD_], g_WvTlo[INNER * CD_];
__device__ __nv_bfloat16 g_WoThi[QD_ * INNER], g_WoTlo[QD_ * INNER];
__device__ __nv_bfloat16 g_AOhi[BNQ * INNER], g_AOlo[BNQ * INNER];

// ---------------------------------------------------------------------------
// PTX helpers (base sm_80/90 features only)
// ---------------------------------------------------------------------------
__device__ __forceinline__ uint32_t smem_u32(const void* p) {
    uint32_t a;
    asm("{ .reg .u64 t; cvta.to.shared.u64 t, %1; cvt.u32.u64 %0, t; }"
        : "=r"(a) : "l"(p));
    return a;
}

__device__ __forceinline__ void cp_async16(uint32_t dst, const void* src) {
    asm volatile("cp.async.cg.shared.global [%0], [%1], 16;"
                 :: "r"(dst), "l"(src) : "memory");
}
#define CP_COMMIT() asm volatile("cp.async.commit_group;" ::: "memory")
#define CP_WAIT(n)  asm volatile("cp.async.wait_group %0;" :: "n"(n) : "memory")

__device__ __forceinline__ void ldmatrix_x4(uint32_t& r0, uint32_t& r1,
                                            uint32_t& r2, uint32_t& r3, uint32_t a) {
    asm volatile("ldmatrix.sync.aligned.m8n8.x4.shared.b16 {%0,%1,%2,%3}, [%4];"
                 : "=r"(r0), "=r"(r1), "=r"(r2), "=r"(r3) : "r"(a));
}

__device__ __forceinline__ void ldmatrix_x4_t(uint32_t& r0, uint32_t& r1,
                                              uint32_t& r2, uint32_t& r3, uint32_t a) {
    asm volatile("ldmatrix.sync.aligned.m8n8.x4.trans.shared.b16 {%0,%1,%2,%3}, [%4];"
                 : "=r"(r0), "=r"(r1), "=r"(r2), "=r"(r3) : "r"(a));
}

__device__ __forceinline__ void mma16816(float* d, const uint32_t* a,
                                         const uint32_t* b) {
    asm volatile(
        "mma.sync.aligned.m16n8k16.row.col.f32.bf16.bf16.f32 "
        "{%0,%1,%2,%3}, {%4,%5,%6,%7}, {%8,%9}, {%0,%1,%2,%3};"
        : "+f"(d[0]), "+f"(d[1]), "+f"(d[2]), "+f"(d[3])
        : "r"(a[0]), "r"(a[1]), "r"(a[2]), "r"(a[3]), "r"(b[0]), "r"(b[1]));
}

// Truncation hi/lo split, packed as bf16x2 (element0 = low half = v0)
__device__ __forceinline__ uint32_t pack_hi2(float v0, float v1) {
    return __byte_perm(__float_as_uint(v0), __float_as_uint(v1), 0x7632);
}
__device__ __forceinline__ uint32_t pack_lo2(float v0, float v1) {
    float l0 = v0 - __uint_as_float(__float_as_uint(v0) & 0xffff0000u);
    float l1 = v1 - __uint_as_float(__float_as_uint(v1) & 0xffff0000u);
    uint32_t r;
    asm("cvt.rn.bf16x2.f32 %0, %1, %2;" : "=r"(r) : "f"(l1), "f"(l0));
    return r;
}

// ---------------------------------------------------------------------------
// Conversion kernels: fp32 -> (hi, lo) bf16 split
// ---------------------------------------------------------------------------
__global__ void cvt_hilo_kernel(const float* __restrict__ in,
                                __nv_bfloat16* __restrict__ hi,
                                __nv_bfloat16* __restrict__ lo, int n4)
{
    int i = blockIdx.x * blockDim.x + threadIdx.x;
    if (i >= n4) return;
    float4 v = reinterpret_cast<const float4*>(in)[i];
    reinterpret_cast<uint32_t*>(hi)[i * 2 + 0] = pack_hi2(v.x, v.y);
    reinterpret_cast<uint32_t*>(hi)[i * 2 + 1] = pack_hi2(v.z, v.w);
    reinterpret_cast<uint32_t*>(lo)[i * 2 + 0] = pack_lo2(v.x, v.y);
    reinterpret_cast<uint32_t*>(lo)[i * 2 + 1] = pack_lo2(v.z, v.w);
}

// W [K,N] row-major  ->  T [N,K] (hi, lo) bf16
__global__ void transpose_cvt_kernel(const float* __restrict__ W,
                                     __nv_bfloat16* __restrict__ Thi,
                                     __nv_bfloat16* __restrict__ Tlo, int K, int N)
{
    __shared__ float t[32][33];
    int tx = threadIdx.x, ty = threadIdx.y;          // 32 x 8
    int n0 = blockIdx.x * 32, k0 = blockIdx.y * 32;
    #pragma unroll
    for (int j = 0; j < 4; ++j)
        t[ty + j * 8][tx] = W[(size_t)(k0 + ty + j * 8) * N + n0 + tx];
    __syncthreads();
    #pragma unroll
    for (int j = 0; j < 4; ++j) {
        float v = t[tx][ty + j * 8];
        int n = n0 + ty + j * 8, k = k0 + tx;
        uint32_t u = __float_as_uint(v);
        float hv = __uint_as_float(u & 0xffff0000u);
        Thi[(size_t)n * K + k] = __ushort_as_bfloat16((unsigned short)(u >> 16));
        Tlo[(size_t)n * K + k] = __float2bfloat16(v - hv);
    }
}

// ---------------------------------------------------------------------------
// mma.sync GEMM: C = A @ B^T (B stored [N,K] K-major), split-bf16 x3.
// 2-stage cp.async pipeline (prefetch distance 1), ONE barrier per K-chunk.
// Loop body: wait(0); sync; stage(ch+1 -> (ch+1)%2); compute(ch <- ch%2).
// The stage copy overlaps compute and has the full compute duration to land.
// BF16OUT: write (hi, lo) bf16 with scale folded; else fp32 (+bias).
// ---------------------------------------------------------------------------
#define SA_        72
#define TILE_B     (128 * SA_ * 2)
#define OFF_AHI    0
#define OFF_ALO    (TILE_B)
#define OFF_BHI    (2 * TILE_B)
#define OFF_BLO    (3 * TILE_B)
#define BUF_B      (4 * TILE_B)             // 73728 per stage
#define GEMM_SMEM  (2 * BUF_B)              // 147456 (matches passing R5 build)

template <bool BF16OUT>
__global__ __launch_bounds__(256) void mma_gemm_kernel(
    const __nv_bfloat16* __restrict__ Ahi, const __nv_bfloat16* __restrict__ Alo,
    const __nv_bfloat16* __restrict__ Bhi, const __nv_bfloat16* __restrict__ Blo,
    float* __restrict__ C, __nv_bfloat16* __restrict__ Chi,
    __nv_bfloat16* __restrict__ Clo, float scale,
    int Ndim, int Kdim, const float* __restrict__ bias)
{
    extern __shared__ __align__(128) char smem[];
    const uint32_t sb = smem_u32(smem);
    const int tid = threadIdx.x, wid = tid >> 5, l = tid & 31;
    const int warp_m = wid >> 2, warp_n = wid & 3;
    const int brow = blockIdx.y * 128, bcol = blockIdx.x * 128;

    const int a_row = warp_m * 64 + (l & 7) + ((l >> 3) & 1) * 8;
    const int a_col = ((l >> 4) & 1) * 8;
    const int b_row = warp_n * 32 + (l & 7) + ((l >> 4) & 1) * 8;
    const int b_col = ((l >> 3) & 1) * 8;
    const uint32_t aOff = (uint32_t)(a_row * SA_ + a_col) * 2;
    const uint32_t bOff = (uint32_t)(b_row * SA_ + b_col) * 2;

    float acc[4][4][4];
    #pragma unroll
    for (int im = 0; im < 4; ++im)
        #pragma unroll
        for (int j = 0; j < 4; ++j)
            #pragma unroll
            for (int q = 0; q < 4; ++q) acc[im][j][q] = 0.f;

    const int nch = Kdim >> 6;

    auto stage = [&](int ch, int bb) {
        const int k0 = ch << 6;
        const uint32_t base = sb + (uint32_t)bb * BUF_B;
        #pragma unroll
        for (int i = 0; i < 4; ++i) {
            int s = tid + i * 256;
            int r = s >> 3, c = s & 7;
            uint32_t so = (uint32_t)(r * 144 + c * 16);
            size_t ga = (size_t)(brow + r) * Kdim + k0 + c * 8;
            size_t gb = (size_t)(bcol + r) * Kdim + k0 + c * 8;
            cp_async16(base + OFF_AHI + so, Ahi + ga);
            cp_async16(base + OFF_ALO + so, Alo + ga);
            cp_async16(base + OFF_BHI + so, Bhi + gb);
            cp_async16(base + OFF_BLO + so, Blo + gb);
        }
        CP_COMMIT();
    };

    stage(0, 0);

    for (int ch = 0; ch < nch; ++ch) {
        CP_WAIT(0);
        __syncthreads();
        // stage(ch+1) writes buffer (ch+1)%2; compute below reads ch%2.
        // (ch+1)%2 was last read by compute(ch-1) -> covered by the barrier.
        if (ch + 1 < nch) stage(ch + 1, (ch + 1) & 1);

        const uint32_t base = sb + (uint32_t)(ch & 1) * BUF_B;
        #pragma unroll
        for (int ks = 0; ks < 4; ++ks) {
            uint32_t ahi[4][4], alo[4][4], bhi[4][2], blo[4][2];
            #pragma unroll
            for (int im = 0; im < 4; ++im) {
                uint32_t ao = aOff + (uint32_t)(im * 16 * SA_ + ks * 16) * 2;
                ldmatrix_x4(ahi[im][0], ahi[im][1], ahi[im][2], ahi[im][3],
                            base + OFF_AHI + ao);
                ldmatrix_x4(alo[im][0], alo[im][1], alo[im][2], alo[im][3],
                            base + OFF_ALO + ao);
            }
            #pragma unroll
            for (int in16 = 0; in16 < 2; ++in16) {
                uint32_t bo = bOff + (uint32_t)(in16 * 16 * SA_ + ks * 16) * 2;
                ldmatrix_x4(bhi[in16 * 2][0], bhi[in16 * 2][1],
                            bhi[in16 * 2 + 1][0], bhi[in16 * 2 + 1][1],
                            base + OFF_BHI + bo);
                ldmatrix_x4(blo[in16 * 2][0], blo[in16 * 2][1],
                            blo[in16 * 2 + 1][0], blo[in16 * 2 + 1][1],
                            base + OFF_BLO + bo);
            }
            #pragma unroll
            for (int im = 0; im < 4; ++im)
                #pragma unroll
                for (int j = 0; j < 4; ++j) {
                    mma16816(acc[im][j], ahi[im], bhi[j]);
                    mma16816(acc[im][j], ahi[im], blo[j]);
                    mma16816(acc[im][j], alo[im], bhi[j]);
                }
        }
    }

    #pragma unroll
    for (int im = 0; im < 4; ++im) {
        int row = brow + warp_m * 64 + im * 16 + (l >> 2);
        #pragma unroll
        for (int j = 0; j < 4; ++j) {
            int col = bcol + warp_n * 32 + j * 8 + (l & 3) * 2;
            if (BF16OUT) {
                float v0 = acc[im][j][0] * scale, v1 = acc[im][j][1] * scale;
                float v2 = acc[im][j][2] * scale, v3 = acc[im][j][3] * scale;
                size_t o0 = (size_t)row * Ndim + col;
                size_t o1 = (size_t)(row + 8) * Ndim + col;
                *reinterpret_cast<uint32_t*>(Chi + o0) = pack_hi2(v0, v1);
                *reinterpret_cast<uint32_t*>(Clo + o0) = pack_lo2(v0, v1);
                *reinterpret_cast<uint32_t*>(Chi + o1) = pack_hi2(v2, v3);
                *reinterpret_cast<uint32_t*>(Clo + o1) = pack_lo2(v2, v3);
            } else {
                float2 v0 = {acc[im][j][0], acc[im][j][1]};
                float2 v1 = {acc[im][j][2], acc[im][j][3]};
                if (bias) {
                    float2 bv = *reinterpret_cast<const float2*>(bias + col);
                    v0.x += bv.x; v0.y += bv.y; v1.x += bv.x; v1.y += bv.y;
                }
                *reinterpret_cast<float2*>(C + (size_t)row * Ndim + col) = v0;
                *reinterpret_cast<float2*>(C + (size_t)(row + 8) * Ndim + col) = v1;
            }
        }
    }
}

// ---------------------------------------------------------------------------
// FA2-style attention, mma.sync, split-bf16 x3 on both matmuls.
// CTA = (b, h, 128 q rows); 8 warps x 16 rows; kv tile = 64, 2-stage pipeline
// (distance 1), ONE barrier per tile. smem/stage: Khi|Klo|Vhi|Vlo (64x72 bf16).
// ---------------------------------------------------------------------------
#define AT_STG    36864
#define AT_SMEM   (2 * AT_STG)              // 73728 (matches passing R5 build)
#define AT_KLO    9216
#define AT_VHI    18432
#define AT_VLO    27648

__global__ __launch_bounds__(256) void attn_mma_kernel(
    const __nv_bfloat16* __restrict__ Qhi, const __nv_bfloat16* __restrict__ Qlo,
    const __nv_bfloat16* __restrict__ Khi, const __nv_bfloat16* __restrict__ Klo,
    const __nv_bfloat16* __restrict__ Vhi, const __nv_bfloat16* __restrict__ Vlo,
    __nv_bfloat16* __restrict__ AOhi, __nv_bfloat16* __restrict__ AOlo)
{
    extern __shared__ __align__(128) char smem[];
    const uint32_t sb = smem_u32(smem);
    const int tid = threadIdx.x, wid = tid >> 5, l = tid & 31;
    const int b = blockIdx.z, h = blockIdx.y;
    const int q0 = blockIdx.x * 128;
    const size_t qrow0 = (size_t)(b * N_ + q0);
    const size_t krow0 = (size_t)(b * M_);
    const int hc = h * 64;

    // ---- Stage Q tile (128 x 64 hi/lo) into stage-0 region, build A frags
    #pragma unroll
    for (int i = 0; i < 4; ++i) {
        int s = tid + i * 256;               // 0..1023
        int r = s >> 3, c = s & 7;
        uint32_t so = (uint32_t)(r * 144 + c * 16);
        size_t g = (qrow0 + r) * INNER + hc + c * 8;
        cp_async16(sb + so, Qhi + g);
        cp_async16(sb + 18432 + so, Qlo + g);
    }
    CP_COMMIT(); CP_WAIT(0);
    __syncthreads();

    uint32_t qh[4][4], ql[4][4];
    {
        int ar = wid * 16 + (l & 7) + ((l >> 3) & 1) * 8;
        int ac = ((l >> 4) & 1) * 8;
        #pragma unroll
        for (int ks = 0; ks < 4; ++ks) {
            uint32_t ad = sb + (uint32_t)(ar * SA_ + ac + ks * 16) * 2;
            ldmatrix_x4(qh[ks][0], qh[ks][1], qh[ks][2], qh[ks][3], ad);
            ldmatrix_x4(ql[ks][0], ql[ks][1], ql[ks][2], ql[ks][3], ad + 18432);
        }
    }
    __syncthreads();

    float o[8][4];
    #pragma unroll
    for (int j = 0; j < 8; ++j)
        #pragma unroll
        for (int q = 0; q < 4; ++q) o[j][q] = 0.f;
    float m0 = -1e30f, m1 = -1e30f, lp0 = 0.f, lp1 = 0.f;

    auto stageKV = [&](int t, int bb) {
        const uint32_t base = sb + (uint32_t)bb * AT_STG;
        const int kv0 = t * 64;
        #pragma unroll
        for (int i = 0; i < 2; ++i) {
            int s = tid + i * 256;           // 0..511
            int r = s >> 3, c = s & 7;
            uint32_t so = (uint32_t)(r * 144 + c * 16);
            size_t g = (krow0 + kv0 + r) * INNER + hc + c * 8;
            cp_async16(base + so,          Khi + g);
            cp_async16(base + AT_KLO + so, Klo + g);
            cp_async16(base + AT_VHI + so, Vhi + g);
            cp_async16(base + AT_VLO + so, Vlo + g);
        }
        CP_COMMIT();
    };

    stageKV(0, 0);

    const int nr  = (l & 7) + ((l >> 4) & 1) * 8;    // K-frag row in tile
    const int kc8 = ((l >> 3) & 1) * 8;              // K-frag col offset
    const int vg  = l >> 3, vi = l & 7;              // V trans-frag coords
    const int NT  = M_ / 64;

    for (int t = 0; t < NT; ++t) {
        CP_WAIT(0);
        __syncthreads();
        if (t + 1 < NT) stageKV(t + 1, (t + 1) & 1);
        const uint32_t kb = sb + (uint32_t)(t & 1) * AT_STG;

        // ---- S = Q K^T (3 split products)
        float s[8][4];
        #pragma unroll
        for (int j = 0; j < 8; ++j)
            #pragma unroll
            for (int q = 0; q < 4; ++q) s[j][q] = 0.f;

        #pragma unroll
        for (int ks = 0; ks < 4; ++ks) {
            #pragma unroll
            for (int jn = 0; jn < 4; ++jn) {
                uint32_t ad = kb + (uint32_t)((jn * 16 + nr) * SA_ + ks * 16 + kc8) * 2;
                uint32_t h0, h1, h2, h3, l0, l1, l2, l3;
                ldmatrix_x4(h0, h1, h2, h3, ad);
                ldmatrix_x4(l0, l1, l2, l3, ad + AT_KLO);
                uint32_t bh0[2] = {h0, h1}, bh1[2] = {h2, h3};
                uint32_t bl0[2] = {l0, l1}, bl1[2] = {l2, l3};
                mma16816(s[2 * jn],     qh[ks], bh0);
                mma16816(s[2 * jn],     qh[ks], bl0);
                mma16816(s[2 * jn],     ql[ks], bh0);
                mma16816(s[2 * jn + 1], qh[ks], bh1);
                mma16816(s[2 * jn + 1], qh[ks], bl1);
                mma16816(s[2 * jn + 1], ql[ks], bh1);
            }
        }

        // ---- online softmax (rows r = l/4 and r+8)
        float mx0 = -1e30f, mx1 = -1e30f;
        #pragma unroll
        for (int j = 0; j < 8; ++j) {
            mx0 = fmaxf(mx0, fmaxf(s[j][0], s[j][1]));
            mx1 = fmaxf(mx1, fmaxf(s[j][2], s[j][3]));
        }
        mx0 = fmaxf(mx0, __shfl_xor_sync(0xffffffffu, mx0, 1));
        mx0 = fmaxf(mx0, __shfl_xor_sync(0xffffffffu, mx0, 2));
        mx1 = fmaxf(mx1, __shfl_xor_sync(0xffffffffu, mx1, 1));
        mx1 = fmaxf(mx1, __shfl_xor_sync(0xffffffffu, mx1, 2));

        float nm0 = fmaxf(m0, mx0), nm1 = fmaxf(m1, mx1);
        float al0 = __expf(m0 - nm0), al1 = __expf(m1 - nm1);
        m0 = nm0; m1 = nm1;

        float add0 = 0.f, add1 = 0.f;
        #pragma unroll
        for (int j = 0; j < 8; ++j) {
            s[j][0] = __expf(s[j][0] - nm0);
            s[j][1] = __expf(s[j][1] - nm0);
            s[j][2] = __expf(s[j][2] - nm1);
            s[j][3] = __expf(s[j][3] - nm1);
            add0 += s[j][0] + s[j][1];
            add1 += s[j][2] + s[j][3];
        }
        lp0 = lp0 * al0 + add0;
        lp1 = lp1 * al1 + add1;
        #pragma unroll
        for (int j = 0; j < 8; ++j) {
            o[j][0] *= al0; o[j][1] *= al0;
            o[j][2] *= al1; o[j][3] *= al1;
        }

        // ---- AV (3 split products), P frags built from s in-registers
        #pragma unroll
        for (int t2 = 0; t2 < 4; ++t2) {
            uint32_t pah[4], pal[4];
            pah[0] = pack_hi2(s[2 * t2][0],     s[2 * t2][1]);
            pah[1] = pack_hi2(s[2 * t2][2],     s[2 * t2][3]);
            pah[2] = pack_hi2(s[2 * t2 + 1][0], s[2 * t2 + 1][1]);
            pah[3] = pack_hi2(s[2 * t2 + 1][2], s[2 * t2 + 1][3]);
            pal[0] = pack_lo2(s[2 * t2][0],     s[2 * t2][1]);
            pal[1] = pack_lo2(s[2 * t2][2],     s[2 * t2][3]);
            pal[2] = pack_lo2(s[2 * t2 + 1][0], s[2 * t2 + 1][1]);
            pal[3] = pack_lo2(s[2 * t2 + 1][2], s[2 * t2 + 1][3]);

            #pragma unroll
            for (int jn = 0; jn < 4; ++jn) {
                uint32_t ad = kb + AT_VHI +
                    (uint32_t)((t2 * 16 + (vg & 1) * 8 + vi) * SA_ +
                               jn * 16 + (vg >> 1) * 8) * 2;
                uint32_t h0, h1, h2, h3, l0, l1, l2, l3;
                ldmatrix_x4_t(h0, h1, h2, h3, ad);
                ldmatrix_x4_t(l0, l1, l2, l3, ad + (AT_VLO - AT_VHI));
                uint32_t bh0[2] = {h0, h1}, bh1[2] = {h2, h3};
                uint32_t bl0[2] = {l0, l1}, bl1[2] = {l2, l3};
                mma16816(o[2 * jn],     pah, bh0);
                mma16816(o[2 * jn],     pah, bl0);
                mma16816(o[2 * jn],     pal, bh0);
                mma16816(o[2 * jn + 1], pah, bh1);
                mma16816(o[2 * jn + 1], pah, bl1);
                mma16816(o[2 * jn + 1], pal, bh1);
            }
        }
    }

    // ---- normalize + write hi/lo bf16
    lp0 += __shfl_xor_sync(0xffffffffu, lp0, 1);
    lp0 += __shfl_xor_sync(0xffffffffu, lp0, 2);
    lp1 += __shfl_xor_sync(0xffffffffu, lp1, 1);
    lp1 += __shfl_xor_sync(0xffffffffu, lp1, 2);
    float inv0 = 1.f / lp0, inv1 = 1.f / lp1;

    size_t r0g = (qrow0 + wid * 16 + (l >> 2)) * INNER + hc;
    size_t r1g = r0g + (size_t)8 * INNER;
    #pragma unroll
    for (int j = 0; j < 8; ++j) {
        int c = j * 8 + (l & 3) * 2;
        float v0 = o[j][0] * inv0, v1 = o[j][1] * inv0;
        float v2 = o[j][2] * inv1, v3 = o[j][3] * inv1;
        *reinterpret_cast<uint32_t*>(AOhi + r0g + c) = pack_hi2(v0, v1);
        *reinterpret_cast<uint32_t*>(AOlo + r0g + c) = pack_lo2(v0, v1);
        *reinterpret_cast<uint32_t*>(AOhi + r1g + c) = pack_hi2(v2, v3);
        *reinterpret_cast<uint32_t*>(AOlo + r1g + c) = pack_lo2(v2, v3);
    }
}

// ---------------------------------------------------------------------------
// Launch
// ---------------------------------------------------------------------------
extern "C" void kernel_launch(void* const* d_in, const int* in_sizes, int n_in,
                              void* d_out, int out_size)
{
    const float* x   = (const float*)d_in[0];
    const float* ctx = (const float*)d_in[1];
    const float* Wq  = (const float*)d_in[2];
    const float* Wk  = (const float*)d_in[3];
    const float* Wv  = (const float*)d_in[4];
    const float* Wo  = (const float*)d_in[5];
    const float* bo  = (const float*)d_in[6];
    float* out = (float*)d_out;

    cudaFuncSetAttribute(mma_gemm_kernel<true>,
                         cudaFuncAttributeMaxDynamicSharedMemorySize, GEMM_SMEM);
    cudaFuncSetAttribute(mma_gemm_kernel<false>,
                         cudaFuncAttributeMaxDynamicSharedMemorySize, GEMM_SMEM);
    cudaFuncSetAttribute(attn_mma_kernel,
                         cudaFuncAttributeMaxDynamicSharedMemorySize, AT_SMEM);

    __nv_bfloat16 *qhi, *qlo, *khi, *klo, *vhi, *vlo;
    __nv_bfloat16 *xhi, *xlo, *chi, *clo, *aohi, *aolo;
    __nv_bfloat16 *wqh, *wql, *wkh, *wkl, *wvh, *wvl, *woh, *wol;
    cudaGetSymbolAddress((void**)&qhi, g_Qhi);  cudaGetSymbolAddress((void**)&qlo, g_Qlo);
    cudaGetSymbolAddress((void**)&khi, g_Khi);  cudaGetSymbolAddress((void**)&klo, g_Klo);
    cudaGetSymbolAddress((void**)&vhi, g_Vhi);  cudaGetSymbolAddress((void**)&vlo, g_Vlo);
    cudaGetSymbolAddress((void**)&xhi, g_xhi);  cudaGetSymbolAddress((void**)&xlo, g_xlo);
    cudaGetSymbolAddress((void**)&chi, g_chi);  cudaGetSymbolAddress((void**)&clo, g_clo);
    cudaGetSymbolAddress((void**)&aohi, g_AOhi); cudaGetSymbolAddress((void**)&aolo, g_AOlo);
    cudaGetSymbolAddress((void**)&wqh, g_WqThi); cudaGetSymbolAddress((void**)&wql, g_WqTlo);
    cudaGetSymbolAddress((void**)&wkh, g_WkThi); cudaGetSymbolAddress((void**)&wkl, g_WkTlo);
    cudaGetSymbolAddress((void**)&wvh, g_WvThi); cudaGetSymbolAddress((void**)&wvl, g_WvTlo);
    cudaGetSymbolAddress((void**)&woh, g_WoThi); cudaGetSymbolAddress((void**)&wol, g_WoTlo);

    // 1. Split-convert inputs
    {
        int n4 = (BNQ * QD_) / 4;
        cvt_hilo_kernel<<<n4 / 256, 256>>>(x, xhi, xlo, n4);
        n4 = (BMC * CD_) / 4;
        cvt_hilo_kernel<<<n4 / 256, 256>>>(ctx, chi, clo, n4);
    }
    transpose_cvt_kernel<<<dim3(INNER / 32, QD_ / 32), dim3(32, 8)>>>(Wq, wqh, wql, QD_, INNER);
    transpose_cvt_kernel<<<dim3(INNER / 32, CD_ / 32), dim3(32, 8)>>>(Wk, wkh, wkl, CD_, INNER);
    transpose_cvt_kernel<<<dim3(INNER / 32, CD_ / 32), dim3(32, 8)>>>(Wv, wvh, wvl, CD_, INNER);
    transpose_cvt_kernel<<<dim3(QD_ / 32, INNER / 32), dim3(32, 8)>>>(Wo, woh, wol, INNER, QD_);

    // 2. Projections -> hi/lo bf16 (Q with softmax scale folded in)
    mma_gemm_kernel<true><<<dim3(INNER / 128, BNQ / 128), 256, GEMM_SMEM>>>(
        xhi, xlo, wqh, wql, nullptr, qhi, qlo, 0.125f, INNER, QD_, nullptr);
    mma_gemm_kernel<true><<<dim3(INNER / 128, BMC / 128), 256, GEMM_SMEM>>>(
        chi, clo, wkh, wkl, nullptr, khi, klo, 1.0f, INNER, CD_, nullptr);
    mma_gemm_kernel<true><<<dim3(INNER / 128, BMC / 128), 256, GEMM_SMEM>>>(
        chi, clo, wvh, wvl, nullptr, vhi, vlo, 1.0f, INNER, CD_, nullptr);

    // 3. Attention (tensor-core FA2)
    attn_mma_kernel<<<dim3(N_ / 128, H_, B_), 256, AT_SMEM>>>(
        qhi, qlo, khi, klo, vhi, vlo, aohi, aolo);

    // 4. Output projection + bias -> d_out (fp32)
    mma_gemm_kernel<false><<<dim3(QD_ / 128, BNQ / 128), 256, GEMM_SMEM>>>(
        aohi, aolo, woh, wol, out, nullptr, nullptr, 1.0f, QD_, INNER, bo);
}